// round 14
// baseline (speedup 1.0000x reference)
#include <cuda_runtime.h>
#include <cuda_bf16.h>
#include <math.h>
#include <stdint.h>

#define H_   16
#define HID_ 1024
#define BL_  4096      /* B*L   */
#define TH_  65536     /* B*L*H */
#define NH_  128       /* gate hidden = 2*D */

// ---------------- device scratch (no allocations) ----------------
// B packed in m16n8k16 fragment order: [ks][n][q] -> uint4 (b0h, b1h, b0l, b1l)
__device__ uint4 g_Bpk[128 * 512];              // 1 MB (128 ksteps over K=2048)
__device__ float g_S[12 * NH_];                 // stat-block column sums
__device__ float g_C1p[4][BL_ * NH_];           // hidden@W1 k-quarter partials (8 MB)

// ---------------- helpers ----------------
__device__ __forceinline__ uint32_t packbf2(float x, float y) {
    __nv_bfloat162 t = __floats2bfloat162_rn(x, y);
    return *(uint32_t*)&t;
}
__device__ __forceinline__ void split2(float x, float y, uint32_t& hi, uint32_t& lo) {
    __nv_bfloat16 hx = __float2bfloat16_rn(x);
    __nv_bfloat16 hy = __float2bfloat16_rn(y);
    __nv_bfloat162 hh = __halves2bfloat162(hx, hy);
    hi = *(uint32_t*)&hh;
    lo = packbf2(x - __bfloat162float(hx), y - __bfloat162float(hy));
}
__device__ __forceinline__ void mma16816(float* d, const uint32_t* a, uint32_t b0, uint32_t b1) {
    asm volatile(
        "mma.sync.aligned.m16n8k16.row.col.f32.bf16.bf16.f32 "
        "{%0,%1,%2,%3}, {%4,%5,%6,%7}, {%8,%9}, {%0,%1,%2,%3};"
        : "+f"(d[0]), "+f"(d[1]), "+f"(d[2]), "+f"(d[3])
        : "r"(a[0]), "r"(a[1]), "r"(a[2]), "r"(a[3]), "r"(b0), "r"(b1));
}

// ---------------- prep (merged): packB (blocks 0..255) + S sums (blocks 256..267) ----------------
__global__ void prep_kernel(const float* __restrict__ W1) {
    int bid = blockIdx.x, tid = threadIdx.x;
    if (bid < 256) {
        int t = bid * 256 + tid;   // 65536
        int q = t & 3, n = (t >> 2) & 127, ks = t >> 9;
        int k0 = ks * 16 + q * 2;
        float a0 = W1[(size_t)k0 * NH_ + n];
        float a1 = W1[(size_t)(k0 + 1) * NH_ + n];
        float a8 = W1[(size_t)(k0 + 8) * NH_ + n];
        float a9 = W1[(size_t)(k0 + 9) * NH_ + n];
        uint32_t h01, l01, h89, l89;
        split2(a0, a1, h01, l01);
        split2(a8, a9, h89, l89);
        g_Bpk[t] = make_uint4(h01, h89, l01, l89);
    } else if (tid < 128) {
        int s = bid - 256, o = tid;
        const float* base = W1 + (size_t)(HID_ + s * 64) * NH_ + o;
        float acc = 0.f;
#pragma unroll
        for (int d = 0; d < 64; d++) acc += base[d * NH_];
        g_S[s * NH_ + o] = acc;
    }
}

// ---------------- g1: C1 partials. One warp = 16 rows x 128 cols. No syncs. ----------------
// grid (64, 4), block 128. CTA: 64 rows; K=256 (k-quarter kq).
__global__ void __launch_bounds__(128, 2) g1_mma(const float* __restrict__ hidden) {
    int tid = threadIdx.x, w = tid >> 5, lane = tid & 31;
    int q = lane & 3, r4 = lane >> 2;
    int kq = blockIdx.y;
    int row0 = blockIdx.x * 64 + w * 16 + r4;
    const float* rb0 = hidden + (size_t)row0 * HID_ + kq * 256 + q * 2;
    const float* rb1 = rb0 + 8 * HID_;

    float acc[16][4];
#pragma unroll
    for (int j = 0; j < 16; j++)
#pragma unroll
        for (int e = 0; e < 4; e++) acc[j][e] = 0.f;

    float2 cv[4];
    cv[0] = *(const float2*)(rb0);
    cv[1] = *(const float2*)(rb0 + 8);
    cv[2] = *(const float2*)(rb1);
    cv[3] = *(const float2*)(rb1 + 8);

#pragma unroll 2
    for (int kl = 0; kl < 16; kl++) {
        float2 nv[4];
        if (kl < 15) {
            nv[0] = *(const float2*)(rb0 + (kl + 1) * 16);
            nv[1] = *(const float2*)(rb0 + (kl + 1) * 16 + 8);
            nv[2] = *(const float2*)(rb1 + (kl + 1) * 16);
            nv[3] = *(const float2*)(rb1 + (kl + 1) * 16 + 8);
        }
        uint32_t Ah[4], Al[4];
        split2(cv[0].x, cv[0].y, Ah[0], Al[0]);
        split2(cv[2].x, cv[2].y, Ah[1], Al[1]);
        split2(cv[1].x, cv[1].y, Ah[2], Al[2]);
        split2(cv[3].x, cv[3].y, Ah[3], Al[3]);
        const uint4* bq = g_Bpk + (size_t)(kq * 16 + kl) * 512 + lane;
#pragma unroll
        for (int j = 0; j < 16; j++) {
            uint4 b = bq[j * 32];
            mma16816(acc[j], Ah, b.x, b.y);
            mma16816(acc[j], Ah, b.z, b.w);
            mma16816(acc[j], Al, b.x, b.y);
        }
#pragma unroll
        for (int e = 0; e < 4; e++) cv[e] = nv[e];
    }
    float* dst = g_C1p[kq];
#pragma unroll
    for (int j = 0; j < 16; j++) {
        int col = j * 8 + q * 2;
        *(float2*)&dst[(size_t)row0 * NH_ + col]       = make_float2(acc[j][0], acc[j][1]);
        *(float2*)&dst[(size_t)(row0 + 8) * NH_ + col] = make_float2(acc[j][2], acc[j][3]);
    }
}

// ---------------- g2: branch GEMM + stat-GEMM ext kstep + fused epilogue ----------------
// grid 1024, block 256. CTA: 64 rows x 128 cols, K=256 + 16(ext).
// A loads pipelined across branches; B fragments register-prefetched depth-1
// across the flattened 16-kstep sequence (addresses static, cross-branch).
__global__ void __launch_bounds__(256, 2) g2_mma(const float* __restrict__ br0,
                                                 const float* __restrict__ br1,
                                                 const float* __restrict__ br2,
                                                 const float* __restrict__ br3,
                                                 const float* __restrict__ b1,
                                                 const float* __restrict__ W2,
                                                 const float* __restrict__ b2v,
                                                 const float* __restrict__ epsf,
                                                 const float* __restrict__ temp,
                                                 float* __restrict__ out) {
    __shared__ uint4 sAh[4][4][32];     // 8 KB  [block][kstep][lane]
    __shared__ uint4 sAl[4][4][32];     // 8 KB
    __shared__ uint4 sBext[512];        // 8 KB  stat-S ext kstep, g_Bpk frag layout
    __shared__ float sC1[4 * NH_];      // 2 KB  (C1 sum + b1)
    __shared__ float sW2[NH_ * 4];      // 2 KB
    __shared__ float sST[64 * 12];      // 3 KB  finalized per-row stats
    __shared__ char  uBuf[2 * 64 * 12 * 4];  // 6 KB union: sSTp then sLog

    float (*sSTp)[64][12] = (float (*)[64][12])uBuf;   // raw per-k-half stat partials
    float (*sLog)[16]     = (float (*)[16])uBuf;       // [64][16] logit partials

    int tid = threadIdx.x, w = tid >> 5, lane = tid & 31;
    int q = lane & 3, r4 = lane >> 2;
    int rg = w >> 2, cq = w & 3;
    int th0 = blockIdx.x * 64;
    int cb = w & 3;         // convert: this warp's 16-row block
    int ckl = w >> 2;       // convert: base kstep (handles ckl and ckl+2)

    // convert-source base offsets (constant across branches)
    size_t coff0 = (size_t)(th0 + cb * 16 + r4) * 64 + ckl * 16 + q * 2;
    size_t coff1 = coff0 + 8 * 64;
    // B fragment base for this warp (kstep 112 = branch k-space start)
    const uint4* bbase = g_Bpk + (size_t)112 * 512 + cq * 128 + lane;

    // ---- preload tables ----
    {
        size_t c0 = (size_t)(th0 >> 4) * NH_;
        for (int i = tid; i < 4 * NH_; i += 256)
            sC1[i] = g_C1p[0][c0 + i] + g_C1p[1][c0 + i] + g_C1p[2][c0 + i] + g_C1p[3][c0 + i]
                   + b1[i & 127];
    }
    for (int i = tid; i < NH_ * 4; i += 256) sW2[i] = W2[i];
    // build stat-S B-ext fragment (rows 0..11 = S, 12..15 = 0)
    for (int t = tid; t < 512; t += 256) {
        int qq = t & 3, n = t >> 2;
        int k0 = qq * 2;
        float v0 = (k0     < 12) ? g_S[(k0)     * NH_ + n] : 0.f;
        float v1 = (k0 + 1 < 12) ? g_S[(k0 + 1) * NH_ + n] : 0.f;
        float v8 = (k0 + 8 < 12) ? g_S[(k0 + 8) * NH_ + n] : 0.f;
        float v9 = (k0 + 9 < 12) ? g_S[(k0 + 9) * NH_ + n] : 0.f;
        uint32_t h01, l01, h89, l89;
        split2(v0, v1, h01, l01);
        split2(v8, v9, h89, l89);
        sBext[t] = make_uint4(h01, h89, l01, l89);
    }

    float acc[2][4][4] = {};

    // ---- prefetch branch 0 convert values + kstep 0 B fragments ----
    float2 pv[2][4];
#pragma unroll
    for (int u = 0; u < 2; u++) {
        const float* rp0 = br0 + coff0 + u * 32;
        const float* rp1 = br0 + coff1 + u * 32;
        pv[u][0] = *(const float2*)(rp0);
        pv[u][1] = *(const float2*)(rp0 + 8);
        pv[u][2] = *(const float2*)(rp1);
        pv[u][3] = *(const float2*)(rp1 + 8);
    }
    uint4 bcur[4];
#pragma unroll
    for (int j = 0; j < 4; j++) bcur[j] = bbase[j * 32];

#pragma unroll 1
    for (int p = 0; p < 4; p++) {
        // ---- convert phase (from prefetched registers) ----
        float sum0 = 0.f, sq0 = 0.f, mx0 = -3.402823466e38f;
        float sum1 = 0.f, sq1 = 0.f, mx1 = -3.402823466e38f;
#pragma unroll
        for (int u = 0; u < 2; u++) {
            int kl = ckl + u * 2;
            float2 v00 = pv[u][0], v01 = pv[u][1], v10 = pv[u][2], v11 = pv[u][3];
            uint4 hi, lo;
            split2(v00.x, v00.y, hi.x, lo.x);
            split2(v10.x, v10.y, hi.y, lo.y);
            split2(v01.x, v01.y, hi.z, lo.z);
            split2(v11.x, v11.y, hi.w, lo.w);
            sAh[cb][kl][lane] = hi;
            sAl[cb][kl][lane] = lo;
            sum0 += v00.x + v00.y + v01.x + v01.y;
            sq0 = fmaf(v00.x, v00.x, fmaf(v00.y, v00.y, fmaf(v01.x, v01.x, fmaf(v01.y, v01.y, sq0))));
            mx0 = fmaxf(mx0, fmaxf(fmaxf(v00.x, v00.y), fmaxf(v01.x, v01.y)));
            sum1 += v10.x + v10.y + v11.x + v11.y;
            sq1 = fmaf(v10.x, v10.x, fmaf(v10.y, v10.y, fmaf(v11.x, v11.x, fmaf(v11.y, v11.y, sq1))));
            mx1 = fmaxf(mx1, fmaxf(fmaxf(v10.x, v10.y), fmaxf(v11.x, v11.y)));
        }
#pragma unroll
        for (int m = 1; m <= 2; m <<= 1) {
            sum0 += __shfl_xor_sync(0xFFFFFFFFu, sum0, m);
            sq0  += __shfl_xor_sync(0xFFFFFFFFu, sq0,  m);
            mx0   = fmaxf(mx0, __shfl_xor_sync(0xFFFFFFFFu, mx0, m));
            sum1 += __shfl_xor_sync(0xFFFFFFFFu, sum1, m);
            sq1  += __shfl_xor_sync(0xFFFFFFFFu, sq1,  m);
            mx1   = fmaxf(mx1, __shfl_xor_sync(0xFFFFFFFFu, mx1, m));
        }
        if (q == 0) {
            sSTp[ckl][cb * 16 + r4][p * 3 + 0] = sum0;
            sSTp[ckl][cb * 16 + r4][p * 3 + 1] = sq0;
            sSTp[ckl][cb * 16 + r4][p * 3 + 2] = mx0;
            sSTp[ckl][cb * 16 + r4 + 8][p * 3 + 0] = sum1;
            sSTp[ckl][cb * 16 + r4 + 8][p * 3 + 1] = sq1;
            sSTp[ckl][cb * 16 + r4 + 8][p * 3 + 2] = mx1;
        }
        __syncthreads();
        // ---- issue next branch's A loads (in flight during mma phase) ----
        if (p < 3) {
            const float* bp = (p == 0) ? br1 : (p == 1) ? br2 : br3;
#pragma unroll
            for (int u = 0; u < 2; u++) {
                const float* rp0 = bp + coff0 + u * 32;
                const float* rp1 = bp + coff1 + u * 32;
                pv[u][0] = *(const float2*)(rp0);
                pv[u][1] = *(const float2*)(rp0 + 8);
                pv[u][2] = *(const float2*)(rp1);
                pv[u][3] = *(const float2*)(rp1 + 8);
            }
        }
        // ---- mma phase (B register-prefetched depth 1, flat kstep index) ----
#pragma unroll
        for (int kl = 0; kl < 4; kl++) {
            int ks = p * 4 + kl;          // 0..15 flat
            uint4 bnxt[4];
            if (ks < 15) {
                const uint4* bn = bbase + (size_t)(ks + 1) * 512;
#pragma unroll
                for (int j = 0; j < 4; j++) bnxt[j] = bn[j * 32];
            }
            uint4 ah0 = sAh[rg * 2][kl][lane];
            uint4 al0 = sAl[rg * 2][kl][lane];
            uint4 ah1 = sAh[rg * 2 + 1][kl][lane];
            uint4 al1 = sAl[rg * 2 + 1][kl][lane];
#pragma unroll
            for (int j = 0; j < 4; j++) {
                mma16816(acc[0][j], &ah0.x, bcur[j].x, bcur[j].y);
                mma16816(acc[0][j], &ah0.x, bcur[j].z, bcur[j].w);
                mma16816(acc[0][j], &al0.x, bcur[j].x, bcur[j].y);
                mma16816(acc[1][j], &ah1.x, bcur[j].x, bcur[j].y);
                mma16816(acc[1][j], &ah1.x, bcur[j].z, bcur[j].w);
                mma16816(acc[1][j], &al1.x, bcur[j].x, bcur[j].y);
            }
#pragma unroll
            for (int j = 0; j < 4; j++) bcur[j] = bnxt[j];
        }
        __syncthreads();
    }

    // ---- finalize stats ----
    if (tid < 64) {
#pragma unroll
        for (int p = 0; p < 4; p++) {
            float sa = sSTp[0][tid][p * 3 + 0] + sSTp[1][tid][p * 3 + 0];
            float sv = sSTp[0][tid][p * 3 + 1] + sSTp[1][tid][p * 3 + 1];
            float mv = fmaxf(sSTp[0][tid][p * 3 + 2], sSTp[1][tid][p * 3 + 2]);
            sST[tid * 12 + p * 3 + 0] = sa * (1.0f / 64.0f);
            sST[tid * 12 + p * 3 + 1] = sqrtf(fmaxf(sv * (1.0f / 64.0f), 1e-8f));
            sST[tid * 12 + p * 3 + 2] = mv;
        }
    }
    __syncthreads();

    // ---- build stat A-ext fragments (warps 0..3, block w) into sAh/sAl[w][0] ----
    if (w < 4) {
        int row0 = w * 16 + r4;
        int k0 = q * 2;
        float v0  = (k0     < 12) ? sST[row0 * 12 + k0]     : 0.f;
        float v1  = (k0 + 1 < 12) ? sST[row0 * 12 + k0 + 1] : 0.f;
        float v8  = (k0 + 8 < 12) ? sST[row0 * 12 + k0 + 8] : 0.f;
        float v9  = (k0 + 9 < 12) ? sST[row0 * 12 + k0 + 9] : 0.f;
        int row1 = row0 + 8;
        float u0  = (k0     < 12) ? sST[row1 * 12 + k0]     : 0.f;
        float u1  = (k0 + 1 < 12) ? sST[row1 * 12 + k0 + 1] : 0.f;
        float u8  = (k0 + 8 < 12) ? sST[row1 * 12 + k0 + 8] : 0.f;
        float u9  = (k0 + 9 < 12) ? sST[row1 * 12 + k0 + 9] : 0.f;
        uint4 hi, lo;
        split2(v0, v1, hi.x, lo.x);
        split2(u0, u1, hi.y, lo.y);
        split2(v8, v9, hi.z, lo.z);
        split2(u8, u9, hi.w, lo.w);
        sAh[w][0][lane] = hi;
        sAl[w][0][lane] = lo;
    }
    __syncthreads();

    // ---- ext kstep: stat GEMM ----
    {
        uint4 ah0 = sAh[rg * 2][0][lane];
        uint4 al0 = sAl[rg * 2][0][lane];
        uint4 ah1 = sAh[rg * 2 + 1][0][lane];
        uint4 al1 = sAl[rg * 2 + 1][0][lane];
        const uint4* bq = sBext + cq * 128 + lane;
#pragma unroll
        for (int j = 0; j < 4; j++) {
            uint4 b = bq[j * 32];
            mma16816(acc[0][j], &ah0.x, b.x, b.y);
            mma16816(acc[0][j], &ah0.x, b.z, b.w);
            mma16816(acc[0][j], &al0.x, b.x, b.y);
            mma16816(acc[1][j], &ah1.x, b.x, b.y);
            mma16816(acc[1][j], &ah1.x, b.z, b.w);
            mma16816(acc[1][j], &al1.x, b.x, b.y);
        }
    }
    __syncthreads();   // before sLog overwrites the union buffer

    // ---- epilogue ----
    float pl[4][4];
#pragma unroll
    for (int s = 0; s < 4; s++)
#pragma unroll
        for (int c = 0; c < 4; c++) pl[s][c] = 0.f;

#pragma unroll
    for (int i = 0; i < 2; i++) {
#pragma unroll
        for (int rr = 0; rr < 2; rr++) {
            int rowc = rg * 32 + i * 16 + r4 + rr * 8;
            int bll = rowc >> 4;
            int slot = i * 2 + rr;
#pragma unroll
            for (int j = 0; j < 4; j++) {
#pragma unroll
                for (int e = 0; e < 2; e++) {
                    int col = cq * 32 + j * 8 + q * 2 + e;
                    float z = acc[i][j][rr * 2 + e] + sC1[bll * NH_ + col];
                    float g = 0.5f * z * (1.0f + erff(z * 0.70710678118654752440f));
                    pl[slot][0] = fmaf(g, sW2[col * 4 + 0], pl[slot][0]);
                    pl[slot][1] = fmaf(g, sW2[col * 4 + 1], pl[slot][1]);
                    pl[slot][2] = fmaf(g, sW2[col * 4 + 2], pl[slot][2]);
                    pl[slot][3] = fmaf(g, sW2[col * 4 + 3], pl[slot][3]);
                }
            }
        }
    }
#pragma unroll
    for (int m = 1; m <= 2; m <<= 1)
#pragma unroll
        for (int s = 0; s < 4; s++)
#pragma unroll
            for (int c = 0; c < 4; c++)
                pl[s][c] += __shfl_xor_sync(0xFFFFFFFFu, pl[s][c], m);
    if (q == 0) {
#pragma unroll
        for (int i = 0; i < 2; i++)
#pragma unroll
            for (int rr = 0; rr < 2; rr++) {
                int rowc = rg * 32 + i * 16 + r4 + rr * 8;
                int slot = i * 2 + rr;
#pragma unroll
                for (int c = 0; c < 4; c++)
                    sLog[rowc][cq * 4 + c] = pl[slot][c];
            }
    }
    __syncthreads();

    if (tid < 64) {
        int th = th0 + tid;
        int h = th & (H_ - 1);
        float l0 = sLog[tid][0] + sLog[tid][4] + sLog[tid][8]  + sLog[tid][12] + b2v[0];
        float l1 = sLog[tid][1] + sLog[tid][5] + sLog[tid][9]  + sLog[tid][13] + b2v[1];
        float l2 = sLog[tid][2] + sLog[tid][6] + sLog[tid][10] + sLog[tid][14] + b2v[2];
        float l3 = sLog[tid][3] + sLog[tid][7] + sLog[tid][11] + sLog[tid][15] + b2v[3];
        float t = fminf(fmaxf(temp[h], 0.2f), 10.0f);
        float inv_t = 1.0f / t;
        float mx = fmaxf(fmaxf(l0, l1), fmaxf(l2, l3));
        float e0 = expf((l0 - mx) * inv_t);
        float e1 = expf((l1 - mx) * inv_t);
        float e2 = expf((l2 - mx) * inv_t);
        float e3 = expf((l3 - mx) * inv_t);
        float inv = 1.0f / (e0 + e1 + e2 + e3);
        float w0 = e0 * inv, w1 = e1 * inv, w2 = e2 * inv, w3 = e3 * inv;
        float f0 = fminf(fmaxf(epsf[h * 4 + 0], 1e-7f), 0.1f);
        float f1 = fminf(fmaxf(epsf[h * 4 + 1], 1e-7f), 0.1f);
        float f2 = fminf(fmaxf(epsf[h * 4 + 2], 1e-7f), 0.1f);
        float f3 = fminf(fmaxf(epsf[h * 4 + 3], 1e-7f), 0.1f);
        w0 = fmaxf(w0, f0); w1 = fmaxf(w1, f1); w2 = fmaxf(w2, f2); w3 = fmaxf(w3, f3);
        float inv2 = 1.0f / (w0 + w1 + w2 + w3);
        ((float4*)out)[th] = make_float4(w0 * inv2, w1 * inv2, w2 * inv2, w3 * inv2);
    }
}

// ---------------- launch ----------------
extern "C" void kernel_launch(void* const* d_in, const int* in_sizes, int n_in,
                              void* d_out, int out_size) {
    const float* hidden = (const float*)d_in[0];
    const float* br0    = (const float*)d_in[1];
    const float* br1    = (const float*)d_in[2];
    const float* br2    = (const float*)d_in[3];
    const float* br3    = (const float*)d_in[4];
    const float* W1     = (const float*)d_in[5];
    const float* b1     = (const float*)d_in[6];
    const float* W2     = (const float*)d_in[7];
    const float* b2v    = (const float*)d_in[8];
    const float* epsf   = (const float*)d_in[9];
    const float* temp   = (const float*)d_in[10];
    float* out = (float*)d_out;

    prep_kernel<<<268, 256>>>(W1);
    g1_mma<<<dim3(64, 4), 128>>>(hidden);
    g2_mma<<<1024, 256>>>(br0, br1, br2, br3, b1, W2, b2v, epsf, temp, out);
}

// round 16
// speedup vs baseline: 1.0989x; 1.0989x over previous
#include <cuda_runtime.h>
#include <cuda_bf16.h>
#include <math.h>
#include <stdint.h>

#define H_   16
#define HID_ 1024
#define BL_  4096      /* B*L   */
#define TH_  65536     /* B*L*H */
#define NH_  128       /* gate hidden = 2*D */

// ---------------- device scratch (no allocations) ----------------
// B packed in m16n8k16 fragment order: [ks][n][q] -> uint4 (b0h, b1h, b0l, b1l)
__device__ uint4 g_Bpk[128 * 512];              // 1 MB (128 ksteps over K=2048)
__device__ float g_S[12 * NH_];                 // stat-block column sums
__device__ float g_C1p[4][BL_ * NH_];           // hidden@W1 k-quarter partials (8 MB)

// ---------------- g2 dynamic smem layout (bytes) ----------------
#define OFF_AH   0                       /* uint4[4][16][32] = 32768 */
#define OFF_AL   32768                   /* 32768 */
#define OFF_BEXT 65536                   /* uint4[512] = 8192 */
#define OFF_C1   73728                   /* float[512]  = 2048 */
#define OFF_W2   75776                   /* float[512]  = 2048 */
#define OFF_ST   77824                   /* float[768]  = 3072 */
#define OFF_UB   80896                   /* union sSTp/sLog = 6144 */
#define G2_SMEM  87040

// ---------------- helpers ----------------
__device__ __forceinline__ uint32_t packbf2(float x, float y) {
    __nv_bfloat162 t = __floats2bfloat162_rn(x, y);
    return *(uint32_t*)&t;
}
__device__ __forceinline__ void split2(float x, float y, uint32_t& hi, uint32_t& lo) {
    __nv_bfloat16 hx = __float2bfloat16_rn(x);
    __nv_bfloat16 hy = __float2bfloat16_rn(y);
    __nv_bfloat162 hh = __halves2bfloat162(hx, hy);
    hi = *(uint32_t*)&hh;
    lo = packbf2(x - __bfloat162float(hx), y - __bfloat162float(hy));
}
__device__ __forceinline__ void mma16816(float* d, const uint32_t* a, uint32_t b0, uint32_t b1) {
    asm volatile(
        "mma.sync.aligned.m16n8k16.row.col.f32.bf16.bf16.f32 "
        "{%0,%1,%2,%3}, {%4,%5,%6,%7}, {%8,%9}, {%0,%1,%2,%3};"
        : "+f"(d[0]), "+f"(d[1]), "+f"(d[2]), "+f"(d[3])
        : "r"(a[0]), "r"(a[1]), "r"(a[2]), "r"(a[3]), "r"(b0), "r"(b1));
}

// ---------------- prep (merged): packB (blocks 0..255) + S sums (blocks 256..267) ----------------
__global__ void prep_kernel(const float* __restrict__ W1) {
    int bid = blockIdx.x, tid = threadIdx.x;
    if (bid < 256) {
        int t = bid * 256 + tid;   // 65536
        int q = t & 3, n = (t >> 2) & 127, ks = t >> 9;
        int k0 = ks * 16 + q * 2;
        float a0 = W1[(size_t)k0 * NH_ + n];
        float a1 = W1[(size_t)(k0 + 1) * NH_ + n];
        float a8 = W1[(size_t)(k0 + 8) * NH_ + n];
        float a9 = W1[(size_t)(k0 + 9) * NH_ + n];
        uint32_t h01, l01, h89, l89;
        split2(a0, a1, h01, l01);
        split2(a8, a9, h89, l89);
        g_Bpk[t] = make_uint4(h01, h89, l01, l89);
    } else if (tid < 128) {
        int s = bid - 256, o = tid;
        const float* base = W1 + (size_t)(HID_ + s * 64) * NH_ + o;
        float acc = 0.f;
#pragma unroll
        for (int d = 0; d < 64; d++) acc += base[d * NH_];
        g_S[s * NH_ + o] = acc;
    }
}

// ---------------- g1: C1 partials. One warp = 16 rows x 128 cols. No syncs. ----------------
// grid (64, 4), block 128. CTA: 64 rows; K=256 (k-quarter kq).
__global__ void __launch_bounds__(128, 2) g1_mma(const float* __restrict__ hidden) {
    int tid = threadIdx.x, w = tid >> 5, lane = tid & 31;
    int q = lane & 3, r4 = lane >> 2;
    int kq = blockIdx.y;
    int row0 = blockIdx.x * 64 + w * 16 + r4;
    const float* rb0 = hidden + (size_t)row0 * HID_ + kq * 256 + q * 2;
    const float* rb1 = rb0 + 8 * HID_;

    float acc[16][4];
#pragma unroll
    for (int j = 0; j < 16; j++)
#pragma unroll
        for (int e = 0; e < 4; e++) acc[j][e] = 0.f;

    float2 cv[4];
    cv[0] = *(const float2*)(rb0);
    cv[1] = *(const float2*)(rb0 + 8);
    cv[2] = *(const float2*)(rb1);
    cv[3] = *(const float2*)(rb1 + 8);

#pragma unroll 2
    for (int kl = 0; kl < 16; kl++) {
        float2 nv[4];
        if (kl < 15) {
            nv[0] = *(const float2*)(rb0 + (kl + 1) * 16);
            nv[1] = *(const float2*)(rb0 + (kl + 1) * 16 + 8);
            nv[2] = *(const float2*)(rb1 + (kl + 1) * 16);
            nv[3] = *(const float2*)(rb1 + (kl + 1) * 16 + 8);
        }
        uint32_t Ah[4], Al[4];
        split2(cv[0].x, cv[0].y, Ah[0], Al[0]);
        split2(cv[2].x, cv[2].y, Ah[1], Al[1]);
        split2(cv[1].x, cv[1].y, Ah[2], Al[2]);
        split2(cv[3].x, cv[3].y, Ah[3], Al[3]);
        const uint4* bq = g_Bpk + (size_t)(kq * 16 + kl) * 512 + lane;
#pragma unroll
        for (int j = 0; j < 16; j++) {
            uint4 b = bq[j * 32];
            mma16816(acc[j], Ah, b.x, b.y);
            mma16816(acc[j], Ah, b.z, b.w);
            mma16816(acc[j], Al, b.x, b.y);
        }
#pragma unroll
        for (int e = 0; e < 4; e++) cv[e] = nv[e];
    }
    float* dst = g_C1p[kq];
#pragma unroll
    for (int j = 0; j < 16; j++) {
        int col = j * 8 + q * 2;
        *(float2*)&dst[(size_t)row0 * NH_ + col]       = make_float2(acc[j][0], acc[j][1]);
        *(float2*)&dst[(size_t)(row0 + 8) * NH_ + col] = make_float2(acc[j][2], acc[j][3]);
    }
}

// ---------------- g2: upfront convert-all, sync-free MMA loop, stat-GEMM ext, fused epilogue ----------------
// grid 1024, block 256, dynamic smem 85 KB. CTA: 64 rows x 128 cols, K=256 + 16(ext).
__global__ void __launch_bounds__(256, 2) g2_mma(const float* __restrict__ br0,
                                                 const float* __restrict__ br1,
                                                 const float* __restrict__ br2,
                                                 const float* __restrict__ br3,
                                                 const float* __restrict__ b1,
                                                 const float* __restrict__ W2,
                                                 const float* __restrict__ b2v,
                                                 const float* __restrict__ epsf,
                                                 const float* __restrict__ temp,
                                                 float* __restrict__ out) {
    extern __shared__ char dyn[];
    uint4 (*sAh)[16][32] = (uint4 (*)[16][32])(dyn + OFF_AH);   // [block][ks][lane]
    uint4 (*sAl)[16][32] = (uint4 (*)[16][32])(dyn + OFF_AL);
    uint4* sBext         = (uint4*)(dyn + OFF_BEXT);
    float* sC1           = (float*)(dyn + OFF_C1);
    float* sW2           = (float*)(dyn + OFF_W2);
    float* sST           = (float*)(dyn + OFF_ST);
    float (*sSTp)[64][12] = (float (*)[64][12])(dyn + OFF_UB);  // union slot A
    float (*sLog)[16]     = (float (*)[16])(dyn + OFF_UB);      // union slot B

    int tid = threadIdx.x, w = tid >> 5, lane = tid & 31;
    int q = lane & 3, r4 = lane >> 2;
    int rg = w >> 2, cq = w & 3;
    int th0 = blockIdx.x * 64;
    int cb = w & 3;          // convert: this warp's 16-row block
    int half = w >> 2;       // convert: kstep parity (ks = half + 2u)

    const float* brs[4] = {br0, br1, br2, br3};

    // ---- preload tables ----
    {
        size_t c0 = (size_t)(th0 >> 4) * NH_;
        for (int i = tid; i < 4 * NH_; i += 256)
            sC1[i] = g_C1p[0][c0 + i] + g_C1p[1][c0 + i] + g_C1p[2][c0 + i] + g_C1p[3][c0 + i]
                   + b1[i & 127];
    }
    for (int i = tid; i < NH_ * 4; i += 256) sW2[i] = W2[i];
    for (int t = tid; t < 512; t += 256) {
        int qq = t & 3, n = t >> 2;
        int k0 = qq * 2;
        float v0 = (k0     < 12) ? g_S[(k0)     * NH_ + n] : 0.f;
        float v1 = (k0 + 1 < 12) ? g_S[(k0 + 1) * NH_ + n] : 0.f;
        float v8 = (k0 + 8 < 12) ? g_S[(k0 + 8) * NH_ + n] : 0.f;
        float v9 = (k0 + 9 < 12) ? g_S[(k0 + 9) * NH_ + n] : 0.f;
        uint32_t h01, l01, h89, l89;
        split2(v0, v1, h01, l01);
        split2(v8, v9, h89, l89);
        sBext[t] = make_uint4(h01, h89, l01, l89);
    }

    // ---- convert ALL branches up front (acc not yet live; regs free for load batching) ----
    {
        float sum0[4] = {}, sq0[4] = {}, sum1[4] = {}, sq1[4] = {};
        float mx0[4], mx1[4];
#pragma unroll
        for (int p = 0; p < 4; p++) { mx0[p] = -3.402823466e38f; mx1[p] = -3.402823466e38f; }
        size_t rowoff0 = (size_t)(th0 + cb * 16 + r4) * 64 + q * 2;
        size_t rowoff1 = rowoff0 + 8 * 64;
#pragma unroll
        for (int u = 0; u < 8; u++) {
            int ks = half + 2 * u;         // 0..15
            int p = ks >> 2;
            int klc = ks & 3;
            const float* bp = brs[p];
            const float* rp0 = bp + rowoff0 + klc * 16;
            const float* rp1 = bp + rowoff1 + klc * 16;
            float2 v00 = *(const float2*)(rp0);
            float2 v01 = *(const float2*)(rp0 + 8);
            float2 v10 = *(const float2*)(rp1);
            float2 v11 = *(const float2*)(rp1 + 8);
            uint4 hi, lo;
            split2(v00.x, v00.y, hi.x, lo.x);
            split2(v10.x, v10.y, hi.y, lo.y);
            split2(v01.x, v01.y, hi.z, lo.z);
            split2(v11.x, v11.y, hi.w, lo.w);
            sAh[cb][ks][lane] = hi;
            sAl[cb][ks][lane] = lo;
            sum0[p] += v00.x + v00.y + v01.x + v01.y;
            sq0[p] = fmaf(v00.x, v00.x, fmaf(v00.y, v00.y, fmaf(v01.x, v01.x, fmaf(v01.y, v01.y, sq0[p]))));
            mx0[p] = fmaxf(mx0[p], fmaxf(fmaxf(v00.x, v00.y), fmaxf(v01.x, v01.y)));
            sum1[p] += v10.x + v10.y + v11.x + v11.y;
            sq1[p] = fmaf(v10.x, v10.x, fmaf(v10.y, v10.y, fmaf(v11.x, v11.x, fmaf(v11.y, v11.y, sq1[p]))));
            mx1[p] = fmaxf(mx1[p], fmaxf(fmaxf(v10.x, v10.y), fmaxf(v11.x, v11.y)));
        }
#pragma unroll
        for (int p = 0; p < 4; p++) {
#pragma unroll
            for (int m = 1; m <= 2; m <<= 1) {
                sum0[p] += __shfl_xor_sync(0xFFFFFFFFu, sum0[p], m);
                sq0[p]  += __shfl_xor_sync(0xFFFFFFFFu, sq0[p],  m);
                mx0[p]   = fmaxf(mx0[p], __shfl_xor_sync(0xFFFFFFFFu, mx0[p], m));
                sum1[p] += __shfl_xor_sync(0xFFFFFFFFu, sum1[p], m);
                sq1[p]  += __shfl_xor_sync(0xFFFFFFFFu, sq1[p],  m);
                mx1[p]   = fmaxf(mx1[p], __shfl_xor_sync(0xFFFFFFFFu, mx1[p], m));
            }
            if (q == 0) {
                sSTp[half][cb * 16 + r4][p * 3 + 0] = sum0[p];
                sSTp[half][cb * 16 + r4][p * 3 + 1] = sq0[p];
                sSTp[half][cb * 16 + r4][p * 3 + 2] = mx0[p];
                sSTp[half][cb * 16 + r4 + 8][p * 3 + 0] = sum1[p];
                sSTp[half][cb * 16 + r4 + 8][p * 3 + 1] = sq1[p];
                sSTp[half][cb * 16 + r4 + 8][p * 3 + 2] = mx1[p];
            }
        }
    }
    __syncthreads();   // sync 1: fragments + stat partials visible

    // ---- finalize stats (warps 0-1; runs while others head into MMA) ----
    if (tid < 64) {
#pragma unroll
        for (int p = 0; p < 4; p++) {
            float sa = sSTp[0][tid][p * 3 + 0] + sSTp[1][tid][p * 3 + 0];
            float sv = sSTp[0][tid][p * 3 + 1] + sSTp[1][tid][p * 3 + 1];
            float mv = fmaxf(sSTp[0][tid][p * 3 + 2], sSTp[1][tid][p * 3 + 2]);
            sST[tid * 12 + p * 3 + 0] = sa * (1.0f / 64.0f);
            sST[tid * 12 + p * 3 + 1] = sqrtf(fmaxf(sv * (1.0f / 64.0f), 1e-8f));
            sST[tid * 12 + p * 3 + 2] = mv;
        }
    }

    // ---- MMA mainloop: 16 ksteps, ZERO syncs ----
    float acc[2][4][4] = {};
#pragma unroll 2
    for (int ks = 0; ks < 16; ks++) {
        uint4 ah0 = sAh[rg * 2][ks][lane];
        uint4 al0 = sAl[rg * 2][ks][lane];
        uint4 ah1 = sAh[rg * 2 + 1][ks][lane];
        uint4 al1 = sAl[rg * 2 + 1][ks][lane];
        const uint4* bq = g_Bpk + (size_t)(112 + ks) * 512 + cq * 128 + lane;
#pragma unroll
        for (int j = 0; j < 4; j++) {
            uint4 b = bq[j * 32];
            mma16816(acc[0][j], &ah0.x, b.x, b.y);
            mma16816(acc[0][j], &ah0.x, b.z, b.w);
            mma16816(acc[0][j], &al0.x, b.x, b.y);
            mma16816(acc[1][j], &ah1.x, b.x, b.y);
            mma16816(acc[1][j], &ah1.x, b.z, b.w);
            mma16816(acc[1][j], &al1.x, b.x, b.y);
        }
    }
    __syncthreads();   // sync 2: MMA done (sAh[.][0] free for reuse), sST final

    // ---- build stat A-ext fragments (warps 0..3, block w) into sAh/sAl[w][0] ----
    if (w < 4) {
        int row0 = w * 16 + r4;
        int k0 = q * 2;
        float v0  = (k0     < 12) ? sST[row0 * 12 + k0]     : 0.f;
        float v1  = (k0 + 1 < 12) ? sST[row0 * 12 + k0 + 1] : 0.f;
        float v8  = (k0 + 8 < 12) ? sST[row0 * 12 + k0 + 8] : 0.f;
        float v9  = (k0 + 9 < 12) ? sST[row0 * 12 + k0 + 9] : 0.f;
        int row1 = row0 + 8;
        float u0  = (k0     < 12) ? sST[row1 * 12 + k0]     : 0.f;
        float u1  = (k0 + 1 < 12) ? sST[row1 * 12 + k0 + 1] : 0.f;
        float u8  = (k0 + 8 < 12) ? sST[row1 * 12 + k0 + 8] : 0.f;
        float u9  = (k0 + 9 < 12) ? sST[row1 * 12 + k0 + 9] : 0.f;
        uint4 hi, lo;
        split2(v0, v1, hi.x, lo.x);
        split2(u0, u1, hi.y, lo.y);
        split2(v8, v9, hi.z, lo.z);
        split2(u8, u9, hi.w, lo.w);
        sAh[w][0][lane] = hi;
        sAl[w][0][lane] = lo;
    }
    __syncthreads();   // sync 3

    // ---- ext kstep: stat GEMM ----
    {
        uint4 ah0 = sAh[rg * 2][0][lane];
        uint4 al0 = sAl[rg * 2][0][lane];
        uint4 ah1 = sAh[rg * 2 + 1][0][lane];
        uint4 al1 = sAl[rg * 2 + 1][0][lane];
        const uint4* bq = sBext + cq * 128 + lane;
#pragma unroll
        for (int j = 0; j < 4; j++) {
            uint4 b = bq[j * 32];
            mma16816(acc[0][j], &ah0.x, b.x, b.y);
            mma16816(acc[0][j], &ah0.x, b.z, b.w);
            mma16816(acc[0][j], &al0.x, b.x, b.y);
            mma16816(acc[1][j], &ah1.x, b.x, b.y);
            mma16816(acc[1][j], &ah1.x, b.z, b.w);
            mma16816(acc[1][j], &al1.x, b.x, b.y);
        }
    }
    __syncthreads();   // sync 4: before sLog overwrites the union buffer

    // ---- epilogue ----
    float pl[4][4];
#pragma unroll
    for (int s = 0; s < 4; s++)
#pragma unroll
        for (int c = 0; c < 4; c++) pl[s][c] = 0.f;

#pragma unroll
    for (int i = 0; i < 2; i++) {
#pragma unroll
        for (int rr = 0; rr < 2; rr++) {
            int rowc = rg * 32 + i * 16 + r4 + rr * 8;
            int bll = rowc >> 4;
            int slot = i * 2 + rr;
#pragma unroll
            for (int j = 0; j < 4; j++) {
#pragma unroll
                for (int e = 0; e < 2; e++) {
                    int col = cq * 32 + j * 8 + q * 2 + e;
                    float z = acc[i][j][rr * 2 + e] + sC1[bll * NH_ + col];
                    float g = 0.5f * z * (1.0f + erff(z * 0.70710678118654752440f));
                    pl[slot][0] = fmaf(g, sW2[col * 4 + 0], pl[slot][0]);
                    pl[slot][1] = fmaf(g, sW2[col * 4 + 1], pl[slot][1]);
                    pl[slot][2] = fmaf(g, sW2[col * 4 + 2], pl[slot][2]);
                    pl[slot][3] = fmaf(g, sW2[col * 4 + 3], pl[slot][3]);
                }
            }
        }
    }
#pragma unroll
    for (int m = 1; m <= 2; m <<= 1)
#pragma unroll
        for (int s = 0; s < 4; s++)
#pragma unroll
            for (int c = 0; c < 4; c++)
                pl[s][c] += __shfl_xor_sync(0xFFFFFFFFu, pl[s][c], m);
    if (q == 0) {
#pragma unroll
        for (int i = 0; i < 2; i++)
#pragma unroll
            for (int rr = 0; rr < 2; rr++) {
                int rowc = rg * 32 + i * 16 + r4 + rr * 8;
                int slot = i * 2 + rr;
#pragma unroll
                for (int c = 0; c < 4; c++)
                    sLog[rowc][cq * 4 + c] = pl[slot][c];
            }
    }
    __syncthreads();   // sync 5

    if (tid < 64) {
        int th = th0 + tid;
        int h = th & (H_ - 1);
        float l0 = sLog[tid][0] + sLog[tid][4] + sLog[tid][8]  + sLog[tid][12] + b2v[0];
        float l1 = sLog[tid][1] + sLog[tid][5] + sLog[tid][9]  + sLog[tid][13] + b2v[1];
        float l2 = sLog[tid][2] + sLog[tid][6] + sLog[tid][10] + sLog[tid][14] + b2v[2];
        float l3 = sLog[tid][3] + sLog[tid][7] + sLog[tid][11] + sLog[tid][15] + b2v[3];
        float t = fminf(fmaxf(temp[h], 0.2f), 10.0f);
        float inv_t = 1.0f / t;
        float mx = fmaxf(fmaxf(l0, l1), fmaxf(l2, l3));
        float e0 = expf((l0 - mx) * inv_t);
        float e1 = expf((l1 - mx) * inv_t);
        float e2 = expf((l2 - mx) * inv_t);
        float e3 = expf((l3 - mx) * inv_t);
        float inv = 1.0f / (e0 + e1 + e2 + e3);
        float w0 = e0 * inv, w1 = e1 * inv, w2 = e2 * inv, w3 = e3 * inv;
        float f0 = fminf(fmaxf(epsf[h * 4 + 0], 1e-7f), 0.1f);
        float f1 = fminf(fmaxf(epsf[h * 4 + 1], 1e-7f), 0.1f);
        float f2 = fminf(fmaxf(epsf[h * 4 + 2], 1e-7f), 0.1f);
        float f3 = fminf(fmaxf(epsf[h * 4 + 3], 1e-7f), 0.1f);
        w0 = fmaxf(w0, f0); w1 = fmaxf(w1, f1); w2 = fmaxf(w2, f2); w3 = fmaxf(w3, f3);
        float inv2 = 1.0f / (w0 + w1 + w2 + w3);
        ((float4*)out)[th] = make_float4(w0 * inv2, w1 * inv2, w2 * inv2, w3 * inv2);
    }
}

// ---------------- launch ----------------
extern "C" void kernel_launch(void* const* d_in, const int* in_sizes, int n_in,
                              void* d_out, int out_size) {
    const float* hidden = (const float*)d_in[0];
    const float* br0    = (const float*)d_in[1];
    const float* br1    = (const float*)d_in[2];
    const float* br2    = (const float*)d_in[3];
    const float* br3    = (const float*)d_in[4];
    const float* W1     = (const float*)d_in[5];
    const float* b1     = (const float*)d_in[6];
    const float* W2     = (const float*)d_in[7];
    const float* b2v    = (const float*)d_in[8];
    const float* epsf   = (const float*)d_in[9];
    const float* temp   = (const float*)d_in[10];
    float* out = (float*)d_out;

    (void)cudaFuncSetAttribute(g2_mma, cudaFuncAttributeMaxDynamicSharedMemorySize, G2_SMEM);

    prep_kernel<<<268, 256>>>(W1);
    g1_mma<<<dim3(64, 4), 128>>>(hidden);
    g2_mma<<<1024, 256, G2_SMEM>>>(br0, br1, br2, br3, b1, W2, b2v, epsf, temp, out);
}